// round 10
// baseline (speedup 1.0000x reference)
#include <cuda_runtime.h>
#include <math_constants.h>

// Problem shape (fixed by reference): B=32, C=8, H=W=256
#define HM        256        // B*C heatmaps
#define HW        65536      // H*W elements per heatmap
#define SL_PER_HM 8          // slices per heatmap
#define NSLICE    (HM * SL_PER_HM)       // 2048 work items
#define SLICE_EL  (HW / SL_PER_HM)       // 8192 elements per slice
#define T1        512                    // threads per block
#define GRID      296                    // 2 blocks/SM x 148 SMs: ONE wave

// Scratch (no device allocation allowed -> __device__ globals, zero-initialized)
__device__ float        g_s [NSLICE];
__device__ float        g_sx[NSLICE];
__device__ float        g_sy[NSLICE];
__device__ float        g_bv[NSLICE];
__device__ int          g_bi[NSLICE];
__device__ unsigned int g_work;    // slice ticket       (reset in epilogue)
__device__ unsigned int g_count;   // blocks-done ticket (reset in epilogue)

// Process 2 quads (u = ubase, ubase+1) of one slice.
__device__ __forceinline__ void compute_group(
    const float4* v, const float4* t, int off0, int tid, int ubase,
    float ybase, float x0,
    float& s, float& sx, float& sy, float& bv, int& bi)
{
    #pragma unroll
    for (int k = 0; k < 2; ++k) {
        const int u = ubase + k;
        const float y = ybase + (float)u * 0.03125f;   // 8/256 per quad-row
        const float e0 = __expf(v[k].x);
        const float e1 = __expf(v[k].y);
        const float e2 = __expf(v[k].z);
        const float e3 = __expf(v[k].w);
        const float es = (e0 + e1) + (e2 + e3);
        s += es;
        sy = fmaf(y, es, sy);
        // sum e_j * x_{w+j} = x0*es + (e1 + 2e2 + 3e3)/256
        sx = fmaf(x0, es,
             fmaf(1.0f / 256.0f, fmaf(3.f, e3, fmaf(2.f, e2, e1)), sx));
        // target argmax with FIRST-index tie-break (rarely-taken branch)
        const float qmax = fmaxf(fmaxf(t[k].x, t[k].y), fmaxf(t[k].z, t[k].w));
        if (qmax > bv) {
            const int off = off0 + (tid + u * T1) * 4;
            bv = qmax;
            bi = (t[k].x == qmax) ? off :
                 (t[k].y == qmax) ? off + 1 :
                 (t[k].z == qmax) ? off + 2 : off + 3;
        }
    }
}

// Persistent fused kernel with register-level double buffering:
// loads for the next group / next slice are always issued BEFORE the compute
// and reduction that would otherwise leave DRAM idle. (R9 showed 40% DRAM-idle
// from lock-stepped load-phase/compute-phase oscillation.)
__global__ __launch_bounds__(T1, 2)
void dsnt_fused(const float* __restrict__ inp, const float* __restrict__ tgt,
                float* __restrict__ out) {
    const int tid = threadIdx.x;
    const int wid = tid >> 5, lid = tid & 31;

    __shared__ float sh_s [T1 / 32];
    __shared__ float sh_sx[T1 / 32];
    __shared__ float sh_sy[T1 / 32];
    __shared__ float sh_bv[T1 / 32];
    __shared__ int   sh_bi[T1 / 32];
    __shared__ int   sh_idx[2];          // ping-pong prefetched work index
    __shared__ unsigned int sh_ticket;

    // x-weight is a per-thread constant: w = (4*tid) & 255
    const float x0 = (float)(((4 * tid) & 255) - 127) * (1.0f / 256.0f);

    if (tid == 0) sh_idx[0] = (int)atomicAdd(&g_work, 1u);
    __syncthreads();
    int par   = 0;
    int s_cur = sh_idx[0];

    float4 vA[2], tA[2], vB[2], tB[2];
    if (s_cur < NSLICE) {                 // preload group A of first slice
        const size_t b = (size_t)(s_cur >> 3) * HW + (s_cur & 7) * SLICE_EL;
        const float4* in4 = (const float4*)(inp + b);
        const float4* tg4 = (const float4*)(tgt + b);
        vA[0] = in4[tid]; vA[1] = in4[tid + T1];
        tA[0] = tg4[tid]; tA[1] = tg4[tid + T1];
    }

    while (s_cur < NSLICE) {
        if (tid == 0) sh_idx[par ^ 1] = (int)atomicAdd(&g_work, 1u);

        const int off0 = (s_cur & 7) * SLICE_EL;
        const size_t base = (size_t)(s_cur >> 3) * HW + off0;
        const float4* in4 = (const float4*)(inp + base);
        const float4* tg4 = (const float4*)(tgt + base);

        // issue group B loads (u=2,3) BEFORE computing group A
        vB[0] = in4[tid + 2 * T1]; vB[1] = in4[tid + 3 * T1];
        tB[0] = tg4[tid + 2 * T1]; tB[1] = tg4[tid + 3 * T1];

        float s = 0.f, sx = 0.f, sy = 0.f;
        float bv = -CUDART_INF_F;
        int   bi = 0x7fffffff;
        const int   hbase = (off0 + 4 * tid) >> 8;
        const float ybase = (float)(hbase - 127) * (1.0f / 256.0f);

        compute_group(vA, tA, off0, tid, 0, ybase, x0, s, sx, sy, bv, bi);

        __syncthreads();                         // publish next ticket
        const int s_nxt = sh_idx[par ^ 1];
        if (s_nxt < NSLICE) {                    // prefetch next slice group A:
            const size_t bn = (size_t)(s_nxt >> 3) * HW + (s_nxt & 7) * SLICE_EL;
            const float4* in4n = (const float4*)(inp + bn);
            const float4* tg4n = (const float4*)(tgt + bn);
            vA[0] = in4n[tid]; vA[1] = in4n[tid + T1];   // in flight across
            tA[0] = tg4n[tid]; tA[1] = tg4n[tid + T1];   // compute B + reduce
        }

        compute_group(vB, tB, off0, tid, 2, ybase, x0, s, sx, sy, bv, bi);

        // ---- block reduction for slice s_cur ----
        #pragma unroll
        for (int o = 16; o > 0; o >>= 1) {
            s  += __shfl_down_sync(0xffffffffu, s,  o);
            sx += __shfl_down_sync(0xffffffffu, sx, o);
            sy += __shfl_down_sync(0xffffffffu, sy, o);
            const float ov = __shfl_down_sync(0xffffffffu, bv, o);
            const int   oi = __shfl_down_sync(0xffffffffu, bi, o);
            if (ov > bv || (ov == bv && oi < bi)) { bv = ov; bi = oi; }
        }
        if (lid == 0) {
            sh_s[wid] = s; sh_sx[wid] = sx; sh_sy[wid] = sy;
            sh_bv[wid] = bv; sh_bi[wid] = bi;
        }
        __syncthreads();
        if (wid == 0) {
            const bool ok = lid < (T1 / 32);
            s  = ok ? sh_s [lid] : 0.f;
            sx = ok ? sh_sx[lid] : 0.f;
            sy = ok ? sh_sy[lid] : 0.f;
            bv = ok ? sh_bv[lid] : -CUDART_INF_F;
            bi = ok ? sh_bi[lid] : 0x7fffffff;
            #pragma unroll
            for (int o = 8; o > 0; o >>= 1) {
                s  += __shfl_down_sync(0xffffffffu, s,  o);
                sx += __shfl_down_sync(0xffffffffu, sx, o);
                sy += __shfl_down_sync(0xffffffffu, sy, o);
                const float ov = __shfl_down_sync(0xffffffffu, bv, o);
                const int   oi = __shfl_down_sync(0xffffffffu, bi, o);
                if (ov > bv || (ov == bv && oi < bi)) { bv = ov; bi = oi; }
            }
            if (lid == 0) {                 // tid0 stores; one release later
                g_s [s_cur] = s;
                g_sx[s_cur] = sx;
                g_sy[s_cur] = sy;
                g_bv[s_cur] = bv;
                g_bi[s_cur] = bi;
            }
        }
        __syncthreads();     // sh_* / sh_idx slot reuse safe next iteration
        par ^= 1;
        s_cur = s_nxt;
    }

    // ---- block done: single release fence + ticket ----
    if (tid == 0) {
        __threadfence();                       // writer-only release (tid0
        sh_ticket = atomicAdd(&g_count, 1u);   // wrote all g_* partials)
    }
    __syncthreads();
    if (sh_ticket != GRID - 1) return;         // not the last block

    // ---- last-block epilogue (256 reading threads) ----
    float m = 0.f;
    if (tid < HM) {
        __threadfence();                 // reader-side acquire (8 warps only)
        float fs = 0.f, fsx = 0.f, fsy = 0.f;
        float fbv = -CUDART_INF_F;
        int   fbi = 0x7fffffff;
        #pragma unroll
        for (int k = 0; k < SL_PER_HM; ++k) {
            const int idx = tid * SL_PER_HM + k;
            fs  += __ldcg(&g_s [idx]);
            fsx += __ldcg(&g_sx[idx]);
            fsy += __ldcg(&g_sy[idx]);
            const float v = __ldcg(&g_bv[idx]);
            const int   i = __ldcg(&g_bi[idx]);
            if (v > fbv || (v == fbv && i < fbi)) { fbv = v; fbi = i; }
        }
        const float inv = 1.0f / fs;
        const float px = fsx * inv;
        const float py = fsy * inv;
        const float tx = (float)((fbi & 255) - 127) * (1.0f / 256.0f);
        const float ty = (float)((fbi >> 8)  - 127) * (1.0f / 256.0f);
        const float dx = px - tx;
        const float dy = py - ty;
        m = 0.5f * (dx * dx + dy * dy);
    }

    // fixed-order reduce of 256 values (tid 256..511 contribute 0)
    #pragma unroll
    for (int o = 16; o > 0; o >>= 1)
        m += __shfl_down_sync(0xffffffffu, m, o);
    __shared__ float sh_m[T1 / 32];
    if (lid == 0) sh_m[wid] = m;
    __syncthreads();
    if (tid == 0) {
        float tot = 0.f;
        #pragma unroll
        for (int w = 0; w < 8; ++w) tot += sh_m[w];   // heatmap warps 0..7 only
        out[0] = tot * (1.0f / 32.0f);                // divide by B
        g_work  = 0;                                   // reset for next replay
        g_count = 0;
    }
}

extern "C" void kernel_launch(void* const* d_in, const int* in_sizes, int n_in,
                              void* d_out, int out_size) {
    const float* inp = (const float*)d_in[0];
    const float* tgt = (const float*)d_in[1];
    float* out = (float*)d_out;
    (void)in_sizes; (void)n_in; (void)out_size;

    dsnt_fused<<<GRID, T1>>>(inp, tgt, out);
}

// round 11
// speedup vs baseline: 1.4906x; 1.4906x over previous
#include <cuda_runtime.h>
#include <cuda.h>
#include <math_constants.h>
#include <cstdint>

// Problem shape (fixed by reference): B=32, C=8, H=W=256
#define HM        256        // B*C heatmaps; ONE BLOCK PER HEATMAP
#define HW        65536      // elements per heatmap
#define T1        512        // threads per block
#define STAGE_EL  2048       // elements per stage per tensor (= T1 float4s)
#define STAGE_B   (STAGE_EL * 4)         // 8192 bytes
#define NIT       (HW / STAGE_EL)        // 32 stage iterations per heatmap
#define DEPTH     2                      // SMEM ring depth (2 x 16KB pair)
#define GRID      HM                     // 256 blocks: single wave, balanced

// Scratch (no device allocation allowed -> __device__ globals, zero-initialized)
__device__ float        g_m[HM];    // per-heatmap MSE
__device__ unsigned int g_count;    // blocks-done ticket; reset in epilogue

__device__ __forceinline__ uint32_t smem_u32(const void* p) {
    return (uint32_t)__cvta_generic_to_shared(p);
}

#define MBAR_INIT(addr, cnt) \
    asm volatile("mbarrier.init.shared.b64 [%0], %1;" :: "r"(addr), "r"(cnt) : "memory")
#define MBAR_EXPECT_TX(addr, bytes) \
    asm volatile("mbarrier.arrive.expect_tx.shared.b64 _, [%0], %1;" \
                 :: "r"(addr), "r"(bytes) : "memory")
// plain (non-tensor) bulk copy global -> shared, completion via mbarrier tx
#define BULK_G2S(dst, src, bytes, mbar) \
    asm volatile("cp.async.bulk.shared::cluster.global.mbarrier::complete_tx::bytes" \
                 " [%0], [%1], %2, [%3];" \
                 :: "r"(dst), "l"(src), "r"(bytes), "r"(mbar) : "memory")

__device__ __forceinline__ void mbar_wait(uint32_t addr, uint32_t parity) {
    asm volatile(
        "{\n\t.reg .pred P;\n\t"
        "WAIT_%=:\n\t"
        "mbarrier.try_wait.parity.acquire.cta.shared::cta.b64 P, [%0], %1, 0x989680;\n\t"
        "@P bra.uni DONE_%=;\n\t"
        "bra.uni WAIT_%=;\n\t"
        "DONE_%=:\n\t}"
        :: "r"(addr), "r"(parity) : "memory");
}

// TMA-pipelined fused DSNT loss kernel. Block b owns heatmap b; a 2-slot SMEM
// ring is fed by cp.async.bulk (TMA engine — load issue decoupled from the
// warp scheduler, which is what kept LDG variants at ~60% DRAM duty).
__global__ __launch_bounds__(T1)
void dsnt_tma(const float* __restrict__ inp, const float* __restrict__ tgt,
              float* __restrict__ out) {
    __shared__ alignas(16) float sm_in[DEPTH][STAGE_EL];   // 16 KB
    __shared__ alignas(16) float sm_tg[DEPTH][STAGE_EL];   // 16 KB
    __shared__ alignas(8)  uint64_t mbar[DEPTH];
    __shared__ float sh_s [T1 / 32];
    __shared__ float sh_sx[T1 / 32];
    __shared__ float sh_sy[T1 / 32];
    __shared__ float sh_bv[T1 / 32];
    __shared__ int   sh_bi[T1 / 32];
    __shared__ unsigned int sh_ticket;

    const int tid = threadIdx.x;
    const int wid = tid >> 5, lid = tid & 31;
    const int hm  = blockIdx.x;
    const float* gin = inp + (size_t)hm * HW;
    const float* gtg = tgt + (size_t)hm * HW;

    const uint32_t mb0 = smem_u32(&mbar[0]);
    const uint32_t mb1 = smem_u32(&mbar[1]);
    const uint32_t din0 = smem_u32(&sm_in[0][0]), din1 = smem_u32(&sm_in[1][0]);
    const uint32_t dtg0 = smem_u32(&sm_tg[0][0]), dtg1 = smem_u32(&sm_tg[1][0]);

    if (tid == 0) {
        MBAR_INIT(mb0, 1);
        MBAR_INIT(mb1, 1);
    }
    __syncthreads();
    if (tid == 0) {      // prologue: issue stages 0 and 1
        MBAR_EXPECT_TX(mb0, 2 * STAGE_B);
        BULK_G2S(din0, gin, STAGE_B, mb0);
        BULK_G2S(dtg0, gtg, STAGE_B, mb0);
        MBAR_EXPECT_TX(mb1, 2 * STAGE_B);
        BULK_G2S(din1, gin + STAGE_EL, STAGE_B, mb1);
        BULK_G2S(dtg1, gtg + STAGE_EL, STAGE_B, mb1);
    }

    // x-weight is a per-thread constant: w = (4*tid) & 255
    const float x0 = (float)(((4 * tid) & 255) - 127) * (1.0f / 256.0f);
    // y row within a stage is fixed per thread: h = it*8 + (tid>>6)
    const int hsub = tid >> 6;

    float s = 0.f, sx = 0.f, sy = 0.f;
    float bv = -CUDART_INF_F;
    int   bi = 0x7fffffff;

    for (int it = 0; it < NIT; ++it) {
        const int slot = it & 1;
        const uint32_t mb = slot ? mb1 : mb0;
        mbar_wait(mb, (it >> 1) & 1);

        const float4 v = ((const float4*)sm_in[slot])[tid];
        const float4 t = ((const float4*)sm_tg[slot])[tid];

        const int off = it * STAGE_EL + tid * 4;        // element idx in heatmap
        const float y = (float)(it * 8 + hsub - 127) * (1.0f / 256.0f);

        const float e0 = __expf(v.x);
        const float e1 = __expf(v.y);
        const float e2 = __expf(v.z);
        const float e3 = __expf(v.w);
        const float es = (e0 + e1) + (e2 + e3);
        s += es;
        sy = fmaf(y, es, sy);
        // sum e_k * x_{w+k} = x0*es + (e1 + 2e2 + 3e3)/256
        sx = fmaf(x0, es,
             fmaf(1.0f / 256.0f, fmaf(3.f, e3, fmaf(2.f, e2, e1)), sx));

        // target argmax, FIRST-index tie-break (rare branch)
        const float qmax = fmaxf(fmaxf(t.x, t.y), fmaxf(t.z, t.w));
        if (qmax > bv) {
            bv = qmax;
            bi = (t.x == qmax) ? off :
                 (t.y == qmax) ? off + 1 :
                 (t.z == qmax) ? off + 2 : off + 3;
        }

        __syncthreads();                      // everyone done reading 'slot'
        if (tid == 0 && it + DEPTH < NIT) {   // reissue slot for stage it+2
            const int nx = it + DEPTH;
            MBAR_EXPECT_TX(mb, 2 * STAGE_B);
            BULK_G2S(slot ? din1 : din0, gin + nx * STAGE_EL, STAGE_B, mb);
            BULK_G2S(slot ? dtg1 : dtg0, gtg + nx * STAGE_EL, STAGE_B, mb);
        }
    }

    // ---- block reduction over the whole heatmap ----
    #pragma unroll
    for (int o = 16; o > 0; o >>= 1) {
        s  += __shfl_down_sync(0xffffffffu, s,  o);
        sx += __shfl_down_sync(0xffffffffu, sx, o);
        sy += __shfl_down_sync(0xffffffffu, sy, o);
        const float ov = __shfl_down_sync(0xffffffffu, bv, o);
        const int   oi = __shfl_down_sync(0xffffffffu, bi, o);
        if (ov > bv || (ov == bv && oi < bi)) { bv = ov; bi = oi; }
    }
    if (lid == 0) {
        sh_s[wid] = s; sh_sx[wid] = sx; sh_sy[wid] = sy;
        sh_bv[wid] = bv; sh_bi[wid] = bi;
    }
    __syncthreads();
    if (wid == 0) {
        const bool ok = lid < (T1 / 32);
        s  = ok ? sh_s [lid] : 0.f;
        sx = ok ? sh_sx[lid] : 0.f;
        sy = ok ? sh_sy[lid] : 0.f;
        bv = ok ? sh_bv[lid] : -CUDART_INF_F;
        bi = ok ? sh_bi[lid] : 0x7fffffff;
        #pragma unroll
        for (int o = 8; o > 0; o >>= 1) {
            s  += __shfl_down_sync(0xffffffffu, s,  o);
            sx += __shfl_down_sync(0xffffffffu, sx, o);
            sy += __shfl_down_sync(0xffffffffu, sy, o);
            const float ov = __shfl_down_sync(0xffffffffu, bv, o);
            const int   oi = __shfl_down_sync(0xffffffffu, bi, o);
            if (ov > bv || (ov == bv && oi < bi)) { bv = ov; bi = oi; }
        }
        if (lid == 0) {
            // per-heatmap MSE directly (block == heatmap)
            const float inv = 1.0f / s;
            const float px = sx * inv;
            const float py = sy * inv;
            const float tx = (float)((bi & 255) - 127) * (1.0f / 256.0f);
            const float ty = (float)((bi >> 8)  - 127) * (1.0f / 256.0f);
            const float dx = px - tx;
            const float dy = py - ty;
            g_m[hm] = 0.5f * (dx * dx + dy * dy);
            __threadfence();                       // writer-only release
            sh_ticket = atomicAdd(&g_count, 1u);
        }
    }
    __syncthreads();
    if (sh_ticket != GRID - 1) return;             // not the last block

    // ---- last-block epilogue: fixed-order sum of 256 heatmap MSEs / B ----
    float m = 0.f;
    if (tid < HM) {
        __threadfence();                           // reader-side acquire
        m = __ldcg(&g_m[tid]);
    }
    #pragma unroll
    for (int o = 16; o > 0; o >>= 1)
        m += __shfl_down_sync(0xffffffffu, m, o);
    __shared__ float sh_m[T1 / 32];
    if (lid == 0) sh_m[wid] = m;
    __syncthreads();
    if (tid == 0) {
        float tot = 0.f;
        #pragma unroll
        for (int w = 0; w < 8; ++w) tot += sh_m[w];   // warps 0..7 hold tids<256
        out[0] = tot * (1.0f / 32.0f);                // divide by B
        g_count = 0;                                   // reset for next replay
    }
}

extern "C" void kernel_launch(void* const* d_in, const int* in_sizes, int n_in,
                              void* d_out, int out_size) {
    const float* inp = (const float*)d_in[0];
    const float* tgt = (const float*)d_in[1];
    float* out = (float*)d_out;
    (void)in_sizes; (void)n_in; (void)out_size;

    dsnt_tma<<<GRID, T1>>>(inp, tgt, out);
}

// round 12
// speedup vs baseline: 1.5724x; 1.0548x over previous
#include <cuda_runtime.h>
#include <math_constants.h>

// Problem shape (fixed by reference): B=32, C=8, H=W=256
#define HM        256        // B*C heatmaps
#define HW        65536      // H*W elements per heatmap
#define SLICES    4          // blocks per heatmap
#define NBLK      (HM * SLICES)          // 1024 blocks
#define SLICE_EL  (HW / SLICES)          // 16384 elements per slice
#define T1        512                    // threads per block
#define V4_PER_T  (SLICE_EL / 4 / T1)    // 8 float4 quads per thread per tensor

// Scratch (no device allocation allowed -> __device__ globals, zero-initialized)
__device__ float        g_s [NBLK];
__device__ float        g_sx[NBLK];
__device__ float        g_sy[NBLK];
__device__ float        g_bv[NBLK];
__device__ int          g_bi[NBLK];
__device__ unsigned int g_count;   // last-block-done ticket; reset each call

// Best-measured configuration (R6: 28.10us kernel): static 1024x512 grid,
// simple rolling loads, fused last-block epilogue with writer-only fencing.
// This round's single delta: __ldcs streaming hints on the two read-once
// streams (clean test; in R5 it was confounded by an all-thread fence bug).
__global__ __launch_bounds__(T1)
void dsnt_fused(const float* __restrict__ inp, const float* __restrict__ tgt,
                float* __restrict__ out) {
    const int blk = blockIdx.x;
    const int hm  = blk >> 2;       // heatmap id
    const int sl  = blk & 3;        // slice id
    const size_t base = (size_t)hm * HW + (size_t)sl * SLICE_EL;
    const float4* __restrict__ in4 = (const float4*)(inp + base);
    const float4* __restrict__ tg4 = (const float4*)(tgt + base);

    const int tid  = threadIdx.x;
    const int off0 = sl * SLICE_EL;      // element offset of slice within heatmap

    float s = 0.f, sx = 0.f, sy = 0.f;
    float bv = -CUDART_INF_F;
    int   bi = 0x7fffffff;

    #pragma unroll
    for (int it = 0; it < V4_PER_T; ++it) {
        const int i4  = tid + it * T1;       // coalesced float4 index in slice
        const float4 v = __ldcs(&in4[i4]);   // streaming: read-once, evict-first
        const float4 t = __ldcs(&tg4[i4]);
        const int off = off0 + i4 * 4;       // element index within heatmap
        const int h   = off >> 8;
        const int w   = off & 255;
        // xs[j] = (j+1-128)/256 = (j-127)/256 ; ys[p] = (p-127)/256
        const float y  = (float)(h - 127) * (1.0f / 256.0f);
        const float x0 = (float)(w - 127) * (1.0f / 256.0f);

        const float e0 = __expf(v.x);
        const float e1 = __expf(v.y);
        const float e2 = __expf(v.z);
        const float e3 = __expf(v.w);
        const float es = (e0 + e1) + (e2 + e3);
        s += es;
        sy = fmaf(y, es, sy);
        // sum e_k * x_{w+k} = x0*es + (e1 + 2e2 + 3e3)/256
        sx = fmaf(x0, es,
             fmaf(1.0f / 256.0f, fmaf(3.f, e3, fmaf(2.f, e2, e1)), sx));

        // argmax with FIRST-index tie-break: fmax tree + rare branch
        const float qmax = fmaxf(fmaxf(t.x, t.y), fmaxf(t.z, t.w));
        if (qmax > bv) {
            bv = qmax;
            bi = (t.x == qmax) ? off :
                 (t.y == qmax) ? off + 1 :
                 (t.z == qmax) ? off + 2 : off + 3;
        }
    }

    // warp reduction
    #pragma unroll
    for (int o = 16; o > 0; o >>= 1) {
        s  += __shfl_down_sync(0xffffffffu, s,  o);
        sx += __shfl_down_sync(0xffffffffu, sx, o);
        sy += __shfl_down_sync(0xffffffffu, sy, o);
        const float ov = __shfl_down_sync(0xffffffffu, bv, o);
        const int   oi = __shfl_down_sync(0xffffffffu, bi, o);
        if (ov > bv || (ov == bv && oi < bi)) { bv = ov; bi = oi; }
    }

    __shared__ float sh_s [T1 / 32];
    __shared__ float sh_sx[T1 / 32];
    __shared__ float sh_sy[T1 / 32];
    __shared__ float sh_bv[T1 / 32];
    __shared__ int   sh_bi[T1 / 32];
    __shared__ unsigned int sh_ticket;
    const int wid = tid >> 5, lid = tid & 31;
    if (lid == 0) {
        sh_s[wid] = s; sh_sx[wid] = sx; sh_sy[wid] = sy;
        sh_bv[wid] = bv; sh_bi[wid] = bi;
    }
    __syncthreads();

    if (wid == 0) {
        const bool ok = lid < (T1 / 32);
        s  = ok ? sh_s [lid] : 0.f;
        sx = ok ? sh_sx[lid] : 0.f;
        sy = ok ? sh_sy[lid] : 0.f;
        bv = ok ? sh_bv[lid] : -CUDART_INF_F;
        bi = ok ? sh_bi[lid] : 0x7fffffff;
        #pragma unroll
        for (int o = 8; o > 0; o >>= 1) {
            s  += __shfl_down_sync(0xffffffffu, s,  o);
            sx += __shfl_down_sync(0xffffffffu, sx, o);
            sy += __shfl_down_sync(0xffffffffu, sy, o);
            const float ov = __shfl_down_sync(0xffffffffu, bv, o);
            const int   oi = __shfl_down_sync(0xffffffffu, bi, o);
            if (ov > bv || (ov == bv && oi < bi)) { bv = ov; bi = oi; }
        }
        if (lid == 0) {
            // single writer: store partials, release-fence, take ticket
            g_s [blk] = s;
            g_sx[blk] = sx;
            g_sy[blk] = sy;
            g_bv[blk] = bv;
            g_bi[blk] = bi;
            __threadfence();                       // writer-only release
            sh_ticket = atomicAdd(&g_count, 1u);
        }
    }
    __syncthreads();
    if (sh_ticket != NBLK - 1) return;   // not the last block

    // ---- last-block epilogue (256 reading threads) ----
    float m = 0.f;
    if (tid < HM) {
        __threadfence();                 // reader-side acquire (8 warps only)
        float fs = 0.f, fsx = 0.f, fsy = 0.f;
        float fbv = -CUDART_INF_F;
        int   fbi = 0x7fffffff;
        #pragma unroll
        for (int k = 0; k < SLICES; ++k) {
            const int idx = tid * SLICES + k;
            fs  += __ldcg(&g_s [idx]);
            fsx += __ldcg(&g_sx[idx]);
            fsy += __ldcg(&g_sy[idx]);
            const float v = __ldcg(&g_bv[idx]);
            const int   i = __ldcg(&g_bi[idx]);
            if (v > fbv || (v == fbv && i < fbi)) { fbv = v; fbi = i; }
        }
        const float inv = 1.0f / fs;
        const float px = fsx * inv;
        const float py = fsy * inv;
        const float tx = (float)((fbi & 255) - 127) * (1.0f / 256.0f);
        const float ty = (float)((fbi >> 8)  - 127) * (1.0f / 256.0f);
        const float dx = px - tx;
        const float dy = py - ty;
        m = 0.5f * (dx * dx + dy * dy);
    }

    // fixed-order reduce of 256 values (tid 256..511 contribute 0)
    #pragma unroll
    for (int o = 16; o > 0; o >>= 1)
        m += __shfl_down_sync(0xffffffffu, m, o);
    __shared__ float sh_m[T1 / 32];
    if (lid == 0) sh_m[wid] = m;
    __syncthreads();
    if (tid == 0) {
        float tot = 0.f;
        #pragma unroll
        for (int w = 0; w < 8; ++w) tot += sh_m[w];   // heatmap warps 0..7 only
        out[0] = tot * (1.0f / 32.0f);                // divide by B
        g_count = 0;                                   // reset for next replay
    }
}

extern "C" void kernel_launch(void* const* d_in, const int* in_sizes, int n_in,
                              void* d_out, int out_size) {
    const float* inp = (const float*)d_in[0];
    const float* tgt = (const float*)d_in[1];
    float* out = (float*)d_out;
    (void)in_sizes; (void)n_in; (void)out_size;

    dsnt_fused<<<NBLK, T1>>>(inp, tgt, out);
}